// round 6
// baseline (speedup 1.0000x reference)
#include <cuda_runtime.h>
#include <cuda_fp16.h>

#define BB 64
#define II 4096
#define CC 32
#define DD 16
#define KD 16

#define NCHUNK 32      // i-chunks for routing partials
#define RITERS 16      // i's per warp per routing CTA: NCHUNK*8*RITERS == II
#define NI 4           // i's per uhat CTA (pipelined)
#define WP 20          // Wsm pitch (floats) -> conflict-free B-fragment LDS
#define XP 20          // xsm pitch (floats) -> conflict-free A-fragment LDS
#define OPH 264        // Osm pitch in halfs (132 words == 4 mod 32: conflict-free)

#define WBUF (256 * WP)            // floats per W buffer
#define XBUF (BB * XP)             // floats per x buffer
// dynamic smem: 2 x (Wbuf + xbuf) f32  +  Osm f16
#define SMEM_UHAT ((2 * (WBUF + XBUF)) * 4 + BB * OPH * 2)

// Scratch (static device globals; no runtime allocation)
__device__ __half g_uhat[(size_t)BB * II * CC * DD];   // 268 MB, layout [b][i][n=c*16+D]
__device__ float  g_spart[NCHUNK][BB * CC * DD];       // partial s, layout [chunk][b][D][c]
__device__ float  g_V[BB * CC * DD];                   // Vsum, layout [b][c][D]

static __device__ __forceinline__ unsigned f2tf32(float a) {
    unsigned r;
    asm("cvt.rna.tf32.f32 %0, %1;" : "=r"(r) : "f"(a));
    return r;
}

#define CP16(dst_u32, src_ptr) \
    asm volatile("cp.async.ca.shared.global [%0], [%1], 16;" \
                 :: "r"(dst_u32), "l"(src_ptr))

// ---------- pass 0 (tensor cores, v4): cp.async double-buffered i-pipeline ----------
// CTA = (i-group of NI, half): 256 threads = 8 warps, covers 64 b x 256 n per i.
// warp = (mt 0..3, ng 0..1). m16n8k8 tf32 mma (cvt at fragment load).
// Epilogue via Osm (conflict-free) -> coalesced 512B/row STG.128.
__global__ __launch_bounds__(256) void uhat_kernel(
    const float* __restrict__ x, const float* __restrict__ w) {
    extern __shared__ float smem[];
    float*  Wsm = smem;                       // [buf][n_local*WP + d]
    float*  xsm = smem + 2 * WBUF;            // [buf][b*XP + d]
    __half* Osm = (__half*)(smem + 2 * WBUF + 2 * XBUF);   // [b*OPH + n_local]

    const int tid  = threadIdx.x;
    const int ig   = blockIdx.x >> 1;
    const int half = blockIdx.x & 1;
    const int i0   = ig * NI;
    const int warp = tid >> 5;
    const int l    = tid & 31;
    const int lr   = l >> 2;     // 0..7
    const int lc   = l & 3;      // 0..3
    const int mt   = warp >> 1;  // 0..3
    const int ng   = warp & 1;   // 0..1

    // per-thread cp.async source/dest precomputation
    // W: thread copies float4 slots t + q*256 (q=0..3): n = slot>>2, d0 = (slot&3)*4
    // x: thread copies (b = tid>>2, chunk = tid&3)
    const int xb = tid >> 2, xch = tid & 3;

    // ---- prologue: issue load for i0 into buf 0 ----
    {
        const float* wsrc = w + (size_t)i0 * 8192 + half * 4096;
        #pragma unroll
        for (int q = 0; q < 4; q++) {
            int slot = tid + q * 256;
            int n = slot >> 2, d0 = (slot & 3) * 4;
            unsigned dst = (unsigned)__cvta_generic_to_shared(&Wsm[n * WP + d0]);
            CP16(dst, wsrc + slot * 4);
        }
        unsigned xdst = (unsigned)__cvta_generic_to_shared(&xsm[xb * XP + xch * 4]);
        CP16(xdst, x + ((size_t)xb * II + i0) * KD + xch * 4);
        asm volatile("cp.async.commit_group;");
    }

    for (int j = 0; j < NI; j++) {
        const int buf  = j & 1;
        const float* Wb = Wsm + buf * WBUF;
        const float* xv = xsm + buf * XBUF;

        // issue next i's load into the other buffer, then wait for current
        if (j + 1 < NI) {
            const int nbuf = buf ^ 1;
            const int ii = i0 + j + 1;
            const float* wsrc = w + (size_t)ii * 8192 + half * 4096;
            #pragma unroll
            for (int q = 0; q < 4; q++) {
                int slot = tid + q * 256;
                int n = slot >> 2, d0 = (slot & 3) * 4;
                unsigned dst = (unsigned)__cvta_generic_to_shared(
                    &Wsm[nbuf * WBUF + n * WP + d0]);
                CP16(dst, wsrc + slot * 4);
            }
            unsigned xdst = (unsigned)__cvta_generic_to_shared(
                &xsm[nbuf * XBUF + xb * XP + xch * 4]);
            CP16(xdst, x + ((size_t)xb * II + ii) * KD + xch * 4);
            asm volatile("cp.async.commit_group;");
            asm volatile("cp.async.wait_group 1;");
        } else {
            asm volatile("cp.async.wait_group 0;");
        }
        __syncthreads();   // current buffer visible to all; Osm stores of j-1 done

        // ---- mma: 16 n-tiles x 2 k-steps (tf32 cvt at fragment load) ----
        float c[16][4];
        #pragma unroll
        for (int nt = 0; nt < 16; nt++)
            { c[nt][0] = 0.f; c[nt][1] = 0.f; c[nt][2] = 0.f; c[nt][3] = 0.f; }

        #pragma unroll
        for (int ks = 0; ks < 2; ks++) {
            int xoff = (16 * mt + lr) * XP + 8 * ks + lc;
            unsigned a0 = f2tf32(xv[xoff]);
            unsigned a1 = f2tf32(xv[xoff + 8 * XP]);
            unsigned a2 = f2tf32(xv[xoff + 4]);
            unsigned a3 = f2tf32(xv[xoff + 8 * XP + 4]);
            #pragma unroll
            for (int nt = 0; nt < 16; nt++) {
                int woff = (128 * ng + 8 * nt + lr) * WP + 8 * ks + lc;
                unsigned b0 = f2tf32(Wb[woff]);
                unsigned b1 = f2tf32(Wb[woff + 4]);
                asm volatile(
                    "mma.sync.aligned.m16n8k8.row.col.f32.tf32.tf32.f32 "
                    "{%0,%1,%2,%3}, {%4,%5,%6,%7}, {%8,%9}, {%0,%1,%2,%3};"
                    : "+f"(c[nt][0]), "+f"(c[nt][1]), "+f"(c[nt][2]), "+f"(c[nt][3])
                    : "r"(a0), "r"(a1), "r"(a2), "r"(a3), "r"(b0), "r"(b1));
            }
        }

        // ---- epilogue: fragments -> Osm (conflict-free banks) ----
        {
            int r0 = 16 * mt + lr, r1 = r0 + 8;
            int nb = 128 * ng + 2 * lc;
            #pragma unroll
            for (int nt = 0; nt < 16; nt++) {
                *(__half2*)&Osm[r0 * OPH + nb + 8 * nt] =
                    __floats2half2_rn(c[nt][0], c[nt][1]);
                *(__half2*)&Osm[r1 * OPH + nb + 8 * nt] =
                    __floats2half2_rn(c[nt][2], c[nt][3]);
            }
        }
        __syncthreads();   // all mma reads + Osm writes done (also guards buffer reuse)

        // ---- store: warp w owns rows 8w..8w+7; per row warp stores 512B contiguous ----
        {
            const int i = i0 + j;
            __half* base = g_uhat + (size_t)i * (CC * DD) + 256 * half + l * 8;
            #pragma unroll
            for (int r = 0; r < 8; r++) {
                int b = 8 * warp + r;
                uint4 v = *(uint4*)&Osm[b * OPH + l * 8];
                *(uint4*)(base + (size_t)b * II * (CC * DD)) = v;
            }
        }
    }
}

// ---------- routing pass: s[b,c,D] = sum_i softmax_c(u . Vsum) * u ----------
__global__ __launch_bounds__(256) void routing_kernel(int pass1) {
    const int b     = blockIdx.y;
    const int chunk = blockIdx.x;
    const int warp  = threadIdx.x >> 5;
    const int c     = threadIdx.x & 31;

    float V[DD];
    if (!pass1) {
        #pragma unroll
        for (int D = 0; D < DD; D++) V[D] = g_V[(b * CC + c) * DD + D];
    }

    float sacc[DD];
    #pragma unroll
    for (int D = 0; D < DD; D++) sacc[D] = 0.0f;

    const int i0 = chunk * (8 * RITERS) + warp * RITERS;
    const uint4* p = (const uint4*)(g_uhat + ((size_t)b * II + i0) * (CC * DD)) + c * 2;

    uint4 q0 = p[0];
    uint4 q1 = p[1];

    #pragma unroll 4
    for (int k = 0; k < RITERS; k++) {
        uint4 n0 = q0, n1 = q1;
        if (k + 1 < RITERS) {
            n0 = p[(k + 1) * 64];
            n1 = p[(k + 1) * 64 + 1];
        }

        float u[DD];
        unsigned rr[8] = {q0.x, q0.y, q0.z, q0.w, q1.x, q1.y, q1.z, q1.w};
        #pragma unroll
        for (int pp = 0; pp < 8; pp++) {
            __half2 h = *reinterpret_cast<__half2*>(&rr[pp]);
            float2 f = __half22float2(h);
            u[2 * pp]     = f.x;
            u[2 * pp + 1] = f.y;
        }

        float cij;
        if (pass1) {
            cij = 1.0f / 32.0f;
        } else {
            float logit = 0.0f;
            #pragma unroll
            for (int D = 0; D < DD; D++) logit = fmaf(u[D], V[D], logit);
            float m = logit;
            #pragma unroll
            for (int off = 16; off > 0; off >>= 1)
                m = fmaxf(m, __shfl_xor_sync(0xffffffffu, m, off));
            float e = __expf(logit - m);
            float ssum = e;
            #pragma unroll
            for (int off = 16; off > 0; off >>= 1)
                ssum += __shfl_xor_sync(0xffffffffu, ssum, off);
            cij = e / ssum;
        }

        #pragma unroll
        for (int D = 0; D < DD; D++) sacc[D] = fmaf(cij, u[D], sacc[D]);

        q0 = n0; q1 = n1;
    }

    __shared__ float red[8][CC * DD];
    #pragma unroll
    for (int D = 0; D < DD; D++) red[warp][D * 32 + c] = sacc[D];
    __syncthreads();

    for (int t = threadIdx.x; t < CC * DD; t += 256) {
        float v = 0.0f;
        #pragma unroll
        for (int wq = 0; wq < 8; wq++) v += red[wq][t];
        g_spart[chunk][b * (CC * DD) + t] = v;   // [chunk][b][D][c]
    }
}

// ---------- squash: one thread per (b,c,D); 16-lane shfl for |s|^2 ----------
__global__ void squash_kernel(float* __restrict__ out, int pass) {
    int t = blockIdx.x * blockDim.x + threadIdx.x;   // (b,c,D), D fastest
    int bc = t >> 4, D = t & 15;
    int b = bc >> 5, c = bc & 31;
    int addr = b * (CC * DD) + D * 32 + c;           // [b][D][c] partial layout

    float s = 0.0f;
    #pragma unroll
    for (int ch = 0; ch < NCHUNK; ch++) s += g_spart[ch][addr];

    float sq = s * s;
    #pragma unroll
    for (int off = 1; off < 16; off <<= 1)
        sq += __shfl_xor_sync(0xffffffffu, sq, off);

    float f = 1.0f / ((1.0f + sq) * sqrtf(sq + 1e-9f));
    float v = s * f;

    if (pass == 0)      g_V[t] = v;
    else if (pass == 1) g_V[t] += v;
    else                out[t] = v;
}

extern "C" void kernel_launch(void* const* d_in, const int* in_sizes, int n_in,
                              void* d_out, int out_size) {
    const float* x = (const float*)d_in[0];
    const float* w = (const float*)d_in[1];
    float* out = (float*)d_out;

    cudaFuncSetAttribute(uhat_kernel, cudaFuncAttributeMaxDynamicSharedMemorySize,
                         SMEM_UHAT);

    uhat_kernel<<<(II / NI) * 2, 256, SMEM_UHAT>>>(x, w);

    routing_kernel<<<dim3(NCHUNK, BB), 256>>>(1);
    squash_kernel<<<128, 256>>>(out, 0);

    routing_kernel<<<dim3(NCHUNK, BB), 256>>>(0);
    squash_kernel<<<128, 256>>>(out, 1);

    routing_kernel<<<dim3(NCHUNK, BB), 256>>>(0);
    squash_kernel<<<128, 256>>>(out, 2);
}

// round 7
// speedup vs baseline: 1.0432x; 1.0432x over previous
#include <cuda_runtime.h>
#include <cuda_fp16.h>

#define BB 64
#define II 4096
#define CC 32
#define DD 16
#define KD 16

#define NCHUNK 32      // i-chunks for routing partials
#define RITERS 16      // i's per warp per routing CTA: NCHUNK*8*RITERS == II
#define OPH 264        // Osm pitch in halfs (132 words == 4 mod 32: conflict-free)

#define WCH1 2050      // Wf chunk1 base (halves): word offset 1025 == 1 mod 32
#define XCH1 514       // xf chunk1 base (halves): word offset 257  == 1 mod 32

// Scratch (static device globals; no runtime allocation)
__device__ __half g_uhat[(size_t)BB * II * CC * DD];   // 268 MB, layout [b][i][n=c*16+D]
__device__ float  g_spart[NCHUNK][BB * CC * DD];       // partial s, layout [chunk][b][D][c]
__device__ float  g_V[BB * CC * DD];                   // Vsum, layout [b][c][D]

// ---------- pass 0 (fp16 tensor cores): u_hat[b,i,n] = sum_d x[b,i,d]*W[i,n,d] ----------
// CTA = (i, half): 256 threads = 8 warps, covers 64 b x 256 n (n-half of 512).
// warp = (mt 0..3, ng 0..1). m16n8k16 fp16 mma, fp32 accum.
// smem fp16 tiles in chunked [k_hi][row][8] layout -> all fragment LDS conflict-free.
// Epilogue via Osm (conflict-free) -> coalesced 512B/row STG.128.
__global__ __launch_bounds__(256, 3) void uhat_kernel(
    const float* __restrict__ x, const float* __restrict__ w) {
    __shared__ __half Wf[4104];        // chunk0 [0,2048), chunk1 [2050,4098)
    __shared__ __half xf[1032];        // chunk0 [0,512),  chunk1 [514,1026)
    __shared__ __half Osm[BB * OPH];   // [b*OPH + n_local]

    const int tid  = threadIdx.x;
    const int i    = blockIdx.x >> 1;
    const int half = blockIdx.x & 1;
    const int warp = tid >> 5;
    const int l    = tid & 31;
    const int lr   = l >> 2;     // groupID 0..7
    const int lc   = l & 3;      // threadID-in-group 0..3
    const int mt   = warp >> 1;  // 0..3
    const int ng   = warp & 1;   // 0..1

    // ---- fill: W slab (256 n x 16 d) and x tile (64 b x 16 d), f32 -> f16 ----
    {
        const float4* w4 = (const float4*)(w + (size_t)i * 8192 + half * 4096);
        #pragma unroll
        for (int q = 0; q < 4; q++) {
            int slot = tid + q * 256;
            int n = slot >> 2, d0 = (slot & 3) * 4;       // covers d0..d0+3
            float4 v = w4[slot];
            int base = (d0 >= 8 ? WCH1 : 0) + n * 8 + (d0 & 7);
            *(__half2*)&Wf[base]     = __floats2half2_rn(v.x, v.y);
            *(__half2*)&Wf[base + 2] = __floats2half2_rn(v.z, v.w);
        }
        {
            int b = tid >> 2, d0 = (tid & 3) * 4;
            const float4* x4 = (const float4*)(x + ((size_t)b * II + i) * KD);
            float4 v = x4[tid & 3];
            int base = (d0 >= 8 ? XCH1 : 0) + b * 8 + (d0 & 7);
            *(__half2*)&xf[base]     = __floats2half2_rn(v.x, v.y);
            *(__half2*)&xf[base + 2] = __floats2half2_rn(v.z, v.w);
        }
    }
    __syncthreads();

    // ---- A fragments (shared across all 16 n-tiles) ----
    unsigned a0, a1, a2, a3;
    {
        int r = 16 * mt + lr;
        a0 = *(unsigned*)&xf[r * 8 + 2 * lc];               // rows r,   k 0..7
        a1 = *(unsigned*)&xf[(r + 8) * 8 + 2 * lc];         // rows r+8, k 0..7
        a2 = *(unsigned*)&xf[XCH1 + r * 8 + 2 * lc];        // rows r,   k 8..15
        a3 = *(unsigned*)&xf[XCH1 + (r + 8) * 8 + 2 * lc];  // rows r+8, k 8..15
    }

    // ---- mma: 16 n-tiles, one m16n8k16 each ----
    float c[16][4];
    #pragma unroll
    for (int nt = 0; nt < 16; nt++)
        { c[nt][0] = 0.f; c[nt][1] = 0.f; c[nt][2] = 0.f; c[nt][3] = 0.f; }

    #pragma unroll
    for (int nt = 0; nt < 16; nt++) {
        int nn = 128 * ng + 8 * nt + lr;
        unsigned b0 = *(unsigned*)&Wf[nn * 8 + 2 * lc];          // k 0..7
        unsigned b1 = *(unsigned*)&Wf[WCH1 + nn * 8 + 2 * lc];   // k 8..15
        asm volatile(
            "mma.sync.aligned.m16n8k16.row.col.f32.f16.f16.f32 "
            "{%0,%1,%2,%3}, {%4,%5,%6,%7}, {%8,%9}, {%0,%1,%2,%3};"
            : "+f"(c[nt][0]), "+f"(c[nt][1]), "+f"(c[nt][2]), "+f"(c[nt][3])
            : "r"(a0), "r"(a1), "r"(a2), "r"(a3), "r"(b0), "r"(b1));
    }

    // ---- epilogue: fragments -> Osm (bank = 4*lr + 4*nt + lc mod 32: conflict-free) ----
    {
        int r0 = 16 * mt + lr, r1 = r0 + 8;
        int nb = 128 * ng + 2 * lc;
        #pragma unroll
        for (int nt = 0; nt < 16; nt++) {
            *(__half2*)&Osm[r0 * OPH + nb + 8 * nt] = __floats2half2_rn(c[nt][0], c[nt][1]);
            *(__half2*)&Osm[r1 * OPH + nb + 8 * nt] = __floats2half2_rn(c[nt][2], c[nt][3]);
        }
    }
    __syncthreads();

    // ---- store: warp w owns rows 8w..8w+7; per row the warp stores 512B contiguous ----
    {
        __half* base = g_uhat + (size_t)i * (CC * DD) + 256 * half + l * 8;
        #pragma unroll
        for (int r = 0; r < 8; r++) {
            int b = 8 * warp + r;
            uint4 v = *(uint4*)&Osm[b * OPH + l * 8];          // LDS.128, stride-4 phases
            *(uint4*)(base + (size_t)b * II * (CC * DD)) = v;  // STG.128, 4 lines/warp
        }
    }
}

// ---------- routing pass: s[b,c,D] = sum_i softmax_c(u . Vsum) * u ----------
__global__ __launch_bounds__(256) void routing_kernel(int pass1) {
    const int b     = blockIdx.y;
    const int chunk = blockIdx.x;
    const int warp  = threadIdx.x >> 5;
    const int c     = threadIdx.x & 31;

    float V[DD];
    if (!pass1) {
        #pragma unroll
        for (int D = 0; D < DD; D++) V[D] = g_V[(b * CC + c) * DD + D];
    }

    float sacc[DD];
    #pragma unroll
    for (int D = 0; D < DD; D++) sacc[D] = 0.0f;

    const int i0 = chunk * (8 * RITERS) + warp * RITERS;
    const uint4* p = (const uint4*)(g_uhat + ((size_t)b * II + i0) * (CC * DD)) + c * 2;

    uint4 q0 = p[0];
    uint4 q1 = p[1];

    #pragma unroll 4
    for (int k = 0; k < RITERS; k++) {
        uint4 n0 = q0, n1 = q1;
        if (k + 1 < RITERS) {
            n0 = p[(k + 1) * 64];
            n1 = p[(k + 1) * 64 + 1];
        }

        float u[DD];
        unsigned rr[8] = {q0.x, q0.y, q0.z, q0.w, q1.x, q1.y, q1.z, q1.w};
        #pragma unroll
        for (int pp = 0; pp < 8; pp++) {
            __half2 h = *reinterpret_cast<__half2*>(&rr[pp]);
            float2 f = __half22float2(h);
            u[2 * pp]     = f.x;
            u[2 * pp + 1] = f.y;
        }

        float cij;
        if (pass1) {
            cij = 1.0f / 32.0f;
        } else {
            float logit = 0.0f;
            #pragma unroll
            for (int D = 0; D < DD; D++) logit = fmaf(u[D], V[D], logit);
            float m = logit;
            #pragma unroll
            for (int off = 16; off > 0; off >>= 1)
                m = fmaxf(m, __shfl_xor_sync(0xffffffffu, m, off));
            float e = __expf(logit - m);
            float ssum = e;
            #pragma unroll
            for (int off = 16; off > 0; off >>= 1)
                ssum += __shfl_xor_sync(0xffffffffu, ssum, off);
            cij = e / ssum;
        }

        #pragma unroll
        for (int D = 0; D < DD; D++) sacc[D] = fmaf(cij, u[D], sacc[D]);

        q0 = n0; q1 = n1;
    }

    __shared__ float red[8][CC * DD];
    #pragma unroll
    for (int D = 0; D < DD; D++) red[warp][D * 32 + c] = sacc[D];
    __syncthreads();

    for (int t = threadIdx.x; t < CC * DD; t += 256) {
        float v = 0.0f;
        #pragma unroll
        for (int wq = 0; wq < 8; wq++) v += red[wq][t];
        g_spart[chunk][b * (CC * DD) + t] = v;   // [chunk][b][D][c]
    }
}

// ---------- squash: one thread per (b,c,D); 16-lane shfl for |s|^2 ----------
__global__ void squash_kernel(float* __restrict__ out, int pass) {
    int t = blockIdx.x * blockDim.x + threadIdx.x;   // (b,c,D), D fastest
    int bc = t >> 4, D = t & 15;
    int b = bc >> 5, c = bc & 31;
    int addr = b * (CC * DD) + D * 32 + c;           // [b][D][c] partial layout

    float s = 0.0f;
    #pragma unroll
    for (int ch = 0; ch < NCHUNK; ch++) s += g_spart[ch][addr];

    float sq = s * s;
    #pragma unroll
    for (int off = 1; off < 16; off <<= 1)
        sq += __shfl_xor_sync(0xffffffffu, sq, off);

    float f = 1.0f / ((1.0f + sq) * sqrtf(sq + 1e-9f));
    float v = s * f;

    if (pass == 0)      g_V[t] = v;
    else if (pass == 1) g_V[t] += v;
    else                out[t] = v;
}

extern "C" void kernel_launch(void* const* d_in, const int* in_sizes, int n_in,
                              void* d_out, int out_size) {
    const float* x = (const float*)d_in[0];
    const float* w = (const float*)d_in[1];
    float* out = (float*)d_out;

    uhat_kernel<<<II * 2, 256>>>(x, w);

    routing_kernel<<<dim3(NCHUNK, BB), 256>>>(1);
    squash_kernel<<<128, 256>>>(out, 0);

    routing_kernel<<<dim3(NCHUNK, BB), 256>>>(0);
    squash_kernel<<<128, 256>>>(out, 1);

    routing_kernel<<<dim3(NCHUNK, BB), 256>>>(0);
    squash_kernel<<<128, 256>>>(out, 2);
}